// round 12
// baseline (speedup 1.0000x reference)
#include <cuda_runtime.h>
#include <cstdint>
#include <cstddef>

#define T_ 512
#define B_ 64
#define F_ 256
#define H_ 1024
#define C_ 257
#define TB 4       // timesteps batched per gates_gemm block
#define NBLK 128   // scan blocks: quad (4i..4i+3) splits K for 32-wide h-tile i
#define NOWN 32    // owner blocks (blockIdx%4==0) -- the only barrier arrivers
#define NCH4 8     // K chunks of 32 per block (256 K per quarter)
#define WROWS 128  // gate-columns per block tile (4 gates x 32 h)
#define WSM_U32 (NCH4 * WROWS * 36)               // 36864 u32 weight slab
#define ZSM_OFF (WSM_U32 + 2 * 64 * 36)           // after A double-buffer
#define SMEM_SCAN ((ZSM_OFF + WROWS * 68) * 4)    // 200704 B dynamic smem

// Scratch (static __device__ arrays: allowed; no allocation APIs used).
__device__ float g_gates[(size_t)T_ * 4 * H_ * B_];  // [T][4][H][B]
__device__ float g_hs[(size_t)T_ * B_ * H_];         // [T][B][H], tf32-valued
__device__ float g_c[B_ * H_];                       // [B][H]
// Pre-converted tf32 recurrent weights, per (scan-block, K-chunk):
// g_wtf[((blk*NCH4 + kc)*WROWS + r)*32 + p]; blk = grp*4 + kq covers
// K quarter kq*256, h-tile grp (32 h); r = gate*32 + hh; p is the PERMUTED
// k position: within each 8-group, k sits at p = (k&3)*2 + (k>>2), so the
// mma B-fragment pair (k, k+4) is adjacent -> one lds.64.
__device__ uint32_t g_wtf[(size_t)4 * H_ * H_];
// Split-K partials: [grp][helper 0..2][tid][32 fragment regs].
__device__ float g_part[NBLK / 4][3][256][32];
// Group handoff flags (monotone across graph replays; compared relatively).
__device__ volatile unsigned int g_pflag[NBLK / 4];

// Grid-barrier state (replay-safe: arrive reset by last arriver; release is
// monotone, compared relatively). Only OWNER blocks arrive; all blocks wait.
__device__ unsigned int g_arrive;
__device__ volatile unsigned int g_release;

__device__ __forceinline__ uint32_t f2tf(float x) {
    uint32_t r;
    asm("cvt.rna.tf32.f32 %0, %1;" : "=r"(r) : "f"(x));
    return r;
}

// Fast tanh: clamped 2x-exp formula. |err| ~1e-6 (clamped tail < 1e-13).
__device__ __forceinline__ float tanh_fast(float x) {
    float xc = fminf(fmaxf(x, -15.0f), 15.0f);
    float e = __expf(2.0f * xc);
    return __fdividef(e - 1.0f, e + 1.0f);
}
__device__ __forceinline__ float sigmoid_fast(float x) {
    return __fdividef(1.0f, 1.0f + __expf(-x));
}

__device__ __forceinline__ void mma8(float* c, uint32_t a0, uint32_t a1, uint32_t a2,
                                     uint32_t a3, uint32_t b0, uint32_t b1) {
    asm volatile(
        "mma.sync.aligned.m16n8k8.row.col.f32.tf32.tf32.f32 "
        "{%0,%1,%2,%3},{%4,%5,%6,%7},{%8,%9},{%0,%1,%2,%3};"
        : "+f"(c[0]), "+f"(c[1]), "+f"(c[2]), "+f"(c[3])
        : "r"(a0), "r"(a1), "r"(a2), "r"(a3), "r"(b0), "r"(b1));
}

// Device-wide step barrier: owners arrive (32 atomics), EVERY block waits for
// the release bump. Safe because helpers produce nothing cross-block except
// g_part, which the group owner consumes BEFORE arriving here, and a helper's
// next overwrite sits behind this release.
__device__ __forceinline__ void step_barrier(int tid, bool arriver) {
    __syncthreads();
    __threadfence();
    if (tid == 0) {
        unsigned int cur = g_release;
        if (arriver) {
            unsigned int old = atomicAdd(&g_arrive, 1u);
            if (old == NOWN - 1) {
                g_arrive = 0;             // no new arrivals until release bumps
                __threadfence();
                atomicAdd((unsigned int*)&g_release, 1u);
            } else {
                while (g_release == cur) {}
            }
        } else {
            while (g_release == cur) {}
        }
    }
    __syncthreads();
    __threadfence();
}

// ---------------------------------------------------------------------------
// Kernel 0: one-time recurrent-weight repack into tf32 (4-way split-K layout
// with the in-group k permutation; destination-indexed: p -> source k).
// ---------------------------------------------------------------------------
__global__ __launch_bounds__(256) void prep_w(
    const float* __restrict__ whf, const float* __restrict__ whi,
    const float* __restrict__ who, const float* __restrict__ whc) {
    size_t idx = (size_t)blockIdx.x * 256 + threadIdx.x;  // < 4*H*H
    int blk = (int)(idx >> 15);         // 128 slabs of 32768
    int rem = (int)(idx & 32767);
    int kc = rem >> 12;                 // chunk 0..7 (4096 elems each)
    int r = (rem >> 5) & 127;           // gate-col within 128-wide tile
    int p = rem & 31;                   // PERMUTED k position within chunk
    int pp = p & 7;
    int k = (p >> 3) * 8 + (pp >> 1) + (pp & 1) * 4;  // inverse permutation
    int g = r >> 5, hh = r & 31;
    int grp = blk >> 2, kq = blk & 3;
    int kglob = kq * 256 + kc * 32 + k;
    int hrow = grp * 32 + hh;
    const float* wp = (g == 0) ? whf : (g == 1) ? whi : (g == 2) ? who : whc;
    g_wtf[idx] = f2tf(wp[(size_t)hrow * H_ + kglob]);
}

// ---------------------------------------------------------------------------
// Kernel 1: gates GEMM.  g_gates[t][g][h][b] = x[t][b][:] . Wg[h][:] + bg[h]
// Grid: (16 h-tiles of 64, 128 t-batches of TB=4). Loop order gate-outer,
// t-inner: each gate's 64 KB weight tile is pulled from L2 once and re-staged
// from L1 for the other TB-1 timesteps (L1 persists within a launch).
// Block tile: 64(b) x 64(h), K=256; microkernel unchanged.
// ---------------------------------------------------------------------------
__global__ __launch_bounds__(256) void gates_gemm(
    const float* __restrict__ x,
    const float* __restrict__ w0, const float* __restrict__ w1,
    const float* __restrict__ w2, const float* __restrict__ w3,
    const float* __restrict__ bb0, const float* __restrict__ bb1,
    const float* __restrict__ bb2, const float* __restrict__ bb3) {
    __shared__ __align__(16) uint32_t sA[64][36];
    __shared__ __align__(16) uint32_t sB[64][36];
    __shared__ float tile[64][65];

    const int t0 = blockIdx.y * TB, h0 = blockIdx.x * 64;
    const int tid = threadIdx.x, lane = tid & 31, w = tid >> 5;
    const int m0 = (w & 3) * 16, n0 = (w >> 2) * 32;

    for (int g = 0; g < 4; g++) {
        const float* wg = (g == 0) ? w0 : (g == 1) ? w1 : (g == 2) ? w2 : w3;
        const float* bg = (g == 0) ? bb0 : (g == 1) ? bb1 : (g == 2) ? bb2 : bb3;

        for (int tt = 0; tt < TB; tt++) {
            const int t = t0 + tt;
            float acc[4][4] = {};

            for (int kc = 0; kc < F_; kc += 32) {
                __syncthreads();
#pragma unroll
                for (int i = 0; i < 2; i++) {
                    int idx = tid + i * 256;
                    int r = idx >> 3, q = idx & 7;
                    float4 v = *(const float4*)
                        &x[((size_t)t * 64 + r) * F_ + kc + q * 4];
                    uint32_t* d = &sA[r][q * 4];
                    d[0] = f2tf(v.x); d[1] = f2tf(v.y);
                    d[2] = f2tf(v.z); d[3] = f2tf(v.w);
                    float4 u = *(const float4*)
                        &wg[(size_t)(h0 + r) * F_ + kc + q * 4];
                    uint32_t* e = &sB[r][q * 4];
                    e[0] = f2tf(u.x); e[1] = f2tf(u.y);
                    e[2] = f2tf(u.z); e[3] = f2tf(u.w);
                }
                __syncthreads();
#pragma unroll
                for (int ks = 0; ks < 4; ks++) {
                    int kk = ks * 8;
                    uint32_t a0 = sA[m0 + (lane >> 2)][kk + (lane & 3)];
                    uint32_t a1 = sA[m0 + (lane >> 2) + 8][kk + (lane & 3)];
                    uint32_t a2 = sA[m0 + (lane >> 2)][kk + (lane & 3) + 4];
                    uint32_t a3 = sA[m0 + (lane >> 2) + 8][kk + (lane & 3) + 4];
#pragma unroll
                    for (int nt = 0; nt < 4; nt++) {
                        int n = n0 + nt * 8;
                        uint32_t b0 = sB[n + (lane >> 2)][kk + (lane & 3)];
                        uint32_t b1 = sB[n + (lane >> 2)][kk + (lane & 3) + 4];
                        mma8(acc[nt], a0, a1, a2, a3, b0, b1);
                    }
                }
            }
            __syncthreads();
#pragma unroll
            for (int nt = 0; nt < 4; nt++) {
                int col = n0 + nt * 8 + (lane & 3) * 2;
                int row = m0 + (lane >> 2);
                tile[row][col] = acc[nt][0];
                tile[row][col + 1] = acc[nt][1];
                tile[row + 8][col] = acc[nt][2];
                tile[row + 8][col + 1] = acc[nt][3];
            }
            __syncthreads();
            // Transposed, coalesced store into [T][4][H][B] layout + bias.
#pragma unroll
            for (int hh = 0; hh < 8; hh++) {
                int h = w * 8 + hh;
                float bv = bg[h0 + h];
                float* dst = &g_gates[(((size_t)t * 4 + g) * H_ + h0 + h) * 64];
                dst[lane] = tile[lane][h] + bv;
                dst[lane + 32] = tile[lane + 32][h] + bv;
            }
        }
    }
}

// ---------------------------------------------------------------------------
// Kernel 2: persistent LSTM scan. 128 blocks (1/SM); quad (4i..4i+3) owns
// 32-wide h-tile i with 4-way split-K (256 K each). Block tile 64(b)x128(j);
// 8 warps of m32n32 (2m x 4n) -> operand smem traffic balanced with tensor.
// Weights resident in smem (144 KB); A double-buffered; separate zsm region.
// Helpers (sub 1..3) ship fragments via g_part + group flag (3 per step);
// owner folds, runs elementwise, writes h & c. Owners-arrive step barrier.
// ---------------------------------------------------------------------------
__global__ __launch_bounds__(256) void lstm_scan() {
    extern __shared__ __align__(16) uint32_t dyn[];
    uint32_t* wsm = dyn;                                // [NCH4*128][36]
    uint32_t (*sA)[64][36] = (uint32_t (*)[64][36])(dyn + WSM_U32);
    float* zsm = (float*)(dyn + ZSM_OFF);               // [128][68]

    const int tid = threadIdx.x, lane = tid & 31, w = tid >> 5;
    const int m0 = (w & 1) * 32;        // 2 m-positions (b)
    const int n0 = (w >> 1) * 32;       // 4 n-positions (j)
    const int grp = blockIdx.x >> 2;
    const int sub = blockIdx.x & 3;
    const bool owner = (sub == 0);
    const int h0 = grp * 32;
    const int koff = sub * 256;

    // Staging indices (two 256-thread waves cover 64 rows x 8 quads).
    const int r_s = tid >> 3, q_s = tid & 7;
    const int r_s2 = (tid + 256) >> 3;
    const uint32_t* wblk = g_wtf + (size_t)blockIdx.x * (NCH4 * WROWS * 32);

    // Per-thread fragment coordinates (mma C mapping), fragment fi = mt*4+nt.
    const int frow = lane >> 2;         // + m0 + mt*16 (+8)
    const int fcol = (lane & 3) * 2;    // + n0 + nt*8 (+1)

    // Replay-safe flag base (read before any helper increment can occur).
    const unsigned int flagbase = g_pflag[grp];

    // One-time weight preload: slab rows (32 u32) -> padded smem rows (36).
    for (int i = tid; i < NCH4 * WROWS * 8; i += 256) {
        int row = i >> 3, s8 = i & 7;
        *(uint4*)&wsm[row * 36 + s8 * 4] =
            *(const uint4*)&wblk[(size_t)row * 32 + s8 * 4];
    }

    // gx fragment for the CURRENT step (owner only).
    float gxr[8][4];
    if (owner) {
#pragma unroll
        for (int mt = 0; mt < 2; mt++)
#pragma unroll
            for (int nt = 0; nt < 4; nt++)
#pragma unroll
                for (int p = 0; p < 4; p++) {
                    int row = m0 + mt * 16 + frow + (p >> 1) * 8;
                    int col = n0 + nt * 8 + fcol + (p & 1);
                    int g = col >> 5, hh = col & 31;
                    gxr[mt * 4 + nt][p] =
                        g_gates[(((size_t)g) * H_ + h0 + hh) * 64 + row];
                }
    }
    __syncthreads();   // wsm visible to all warps before any mma

    for (int t = 0; t < T_; t++) {
        float acc[8][4] = {};

        if (t > 0) {
            const uint32_t* hp =
                (const uint32_t*)&g_hs[(size_t)(t - 1) * B_ * H_] + koff;

            // Prologue: stage A chunk 0 (h_prev -- the only dependency).
            *(uint4*)&sA[0][r_s][q_s * 4] =
                *(const uint4*)&hp[(size_t)r_s * H_ + q_s * 4];
            *(uint4*)&sA[0][r_s2][q_s * 4] =
                *(const uint4*)&hp[(size_t)r_s2 * H_ + q_s * 4];
            __syncthreads();

            for (int kc = 0; kc < NCH4; kc++) {
                const int cur = kc & 1, nxt = cur ^ 1;
                uint4 va0, va1;
                if (kc < NCH4 - 1) {
                    int k0 = (kc + 1) * 32;
                    va0 = *(const uint4*)&hp[(size_t)r_s * H_ + k0 + q_s * 4];
                    va1 = *(const uint4*)&hp[(size_t)r_s2 * H_ + k0 + q_s * 4];
                }
                const uint32_t* wrow = &wsm[kc * WROWS * 36];
#pragma unroll
                for (int ks = 0; ks < 4; ks++) {
                    int kk = ks * 8;
#pragma unroll
                    for (int mt = 0; mt < 2; mt++) {
                        int mr = m0 + mt * 16 + frow;
                        uint32_t a0 = sA[cur][mr][kk + (lane & 3)];
                        uint32_t a1 = sA[cur][mr + 8][kk + (lane & 3)];
                        uint32_t a2 = sA[cur][mr][kk + (lane & 3) + 4];
                        uint32_t a3 = sA[cur][mr + 8][kk + (lane & 3) + 4];
#pragma unroll
                        for (int nt = 0; nt < 4; nt++) {
                            int n = n0 + nt * 8;
                            // Permuted resident weights: (k,k+4) -> lds.64.
                            uint2 bb = *(const uint2*)
                                &wrow[(n + frow) * 36 + kk + (lane & 3) * 2];
                            mma8(acc[mt * 4 + nt], a0, a1, a2, a3, bb.x, bb.y);
                        }
                    }
                }
                if (kc < NCH4 - 1) {
                    *(uint4*)&sA[nxt][r_s][q_s * 4] = va0;
                    *(uint4*)&sA[nxt][r_s2][q_s * 4] = va1;
                }
                __syncthreads();
            }
        } else {
            __syncthreads();
        }

        if (!owner) {
            // Helper: ship fragment, bump group flag, wait at the barrier.
            if (t > 0) {
                float* dst = g_part[grp][sub - 1][tid];
#pragma unroll
                for (int fi = 0; fi < 8; fi++)
                    *(float4*)&dst[fi * 4] = *(float4*)acc[fi];
                __syncthreads();
                if (tid == 0) {
                    __threadfence();
                    atomicAdd((unsigned int*)&g_pflag[grp], 1u);
                }
            }
        } else {
            // Owner: fold in the 3 helpers' partials, then elementwise.
            if (t > 0) {
                if (tid == 0) {
                    while ((unsigned int)(g_pflag[grp] - flagbase) <
                           3u * (unsigned int)t) {}
                }
                __syncthreads();
                __threadfence();
#pragma unroll
                for (int hlp = 0; hlp < 3; hlp++) {
                    const float* src = g_part[grp][hlp][tid];
#pragma unroll
                    for (int fi = 0; fi < 8; fi++) {
                        float4 pv = *(const float4*)&src[fi * 4];
                        acc[fi][0] += pv.x; acc[fi][1] += pv.y;
                        acc[fi][2] += pv.z; acc[fi][3] += pv.w;
                    }
                }
            }

            // z = gx + rec into zsm[col*68 + row] (col = j, row = b).
#pragma unroll
            for (int mt = 0; mt < 2; mt++)
#pragma unroll
                for (int nt = 0; nt < 4; nt++) {
                    int fi = mt * 4 + nt;
                    int row = m0 + mt * 16 + frow;
                    int col = n0 + nt * 8 + fcol;
                    zsm[(size_t)col * 68 + row] = acc[fi][0] + gxr[fi][0];
                    zsm[(size_t)(col + 1) * 68 + row] = acc[fi][1] + gxr[fi][1];
                    zsm[(size_t)col * 68 + row + 8] = acc[fi][2] + gxr[fi][2];
                    zsm[(size_t)(col + 1) * 68 + row + 8] = acc[fi][3] + gxr[fi][3];
                }
            __syncthreads();

            // Fused elementwise cell update over 32 h x 64 b. j = g*32 + h;
            // gate order f, i, o, a. Fast-math err ~1e-6 << tf32 budget.
            const int b = tid >> 2, hsub = tid & 3;
#pragma unroll
            for (int ii = 0; ii < 8; ii++) {
                int h = hsub + ii * 4;  // 0..31
                float zf = zsm[(size_t)h * 68 + b];
                float zi = zsm[(size_t)(32 + h) * 68 + b];
                float zo = zsm[(size_t)(64 + h) * 68 + b];
                float za = zsm[(size_t)(96 + h) * 68 + b];
                float ft = sigmoid_fast(zf);
                float it = sigmoid_fast(zi);
                float ot = sigmoid_fast(zo);
                int hidx = h0 + h;
                float cold = (t == 0) ? 0.0f : g_c[b * H_ + hidx];
                float cn = it * tanh_fast(za) + ft * cold;
                float hn = ot * tanh_fast(cn);
                g_c[b * H_ + hidx] = cn;
                // tf32-rounded h: next step's A staging is a raw bit copy.
                g_hs[((size_t)t * B_ + b) * H_ + hidx] =
                    __uint_as_float(f2tf(hn));
            }
        }

        if (t < T_ - 1) {
            // Cross-barrier prefetch of next step's gx (static source).
            if (owner) {
#pragma unroll
                for (int mt = 0; mt < 2; mt++)
#pragma unroll
                    for (int nt = 0; nt < 4; nt++)
#pragma unroll
                        for (int p = 0; p < 4; p++) {
                            int row = m0 + mt * 16 + frow + (p >> 1) * 8;
                            int col = n0 + nt * 8 + fcol + (p & 1);
                            int g = col >> 5, hh = col & 31;
                            gxr[mt * 4 + nt][p] = g_gates[
                                (((size_t)(t + 1) * 4 + g) * H_ + h0 + hh) * 64
                                + row];
                        }
            }
            step_barrier(tid, owner);
        }
    }
}

// ---------------------------------------------------------------------------
// Kernel 3: output GEMM.  out[row][c] = hs[row][:] . fco_w[c][:] + fco_b[c]
// Grid: (5 n-tiles of 64 covering C=257, 512 m-tiles of 64).
// ---------------------------------------------------------------------------
__global__ __launch_bounds__(256) void out_gemm(
    const float* __restrict__ wco, const float* __restrict__ bco,
    float* __restrict__ out) {
    __shared__ __align__(16) uint32_t sA[64][36];
    __shared__ __align__(16) uint32_t sB[64][36];
    __shared__ float tile[64][65];

    const int r0 = blockIdx.y * 64;
    const int n0g = blockIdx.x * 64;
    const int tid = threadIdx.x, lane = tid & 31, w = tid >> 5;
    const int m0 = (w & 3) * 16, n0 = (w >> 2) * 32;
    float acc[4][4] = {};

    for (int kc = 0; kc < H_; kc += 32) {
        __syncthreads();
#pragma unroll
        for (int i = 0; i < 2; i++) {
            int idx = tid + i * 256;
            int r = idx >> 3, q = idx & 7;
            *(uint4*)&sA[r][q * 4] = *(const uint4*)
                &g_hs[(size_t)(r0 + r) * H_ + kc + q * 4];
            int nr = n0g + r;
            float4 u = (nr < C_) ? *(const float4*)&wco[(size_t)nr * H_ + kc + q * 4]
                                 : make_float4(0.f, 0.f, 0.f, 0.f);
            uint32_t* e = &sB[r][q * 4];
            e[0] = f2tf(u.x); e[1] = f2tf(u.y); e[2] = f2tf(u.z); e[3] = f2tf(u.w);
        }
        __syncthreads();
#pragma unroll
        for (int ks = 0; ks < 4; ks++) {
            int kk = ks * 8;
            uint32_t a0 = sA[m0 + (lane >> 2)][kk + (lane & 3)];
            uint32_t a1 = sA[m0 + (lane >> 2) + 8][kk + (lane & 3)];
            uint32_t a2 = sA[m0 + (lane >> 2)][kk + (lane & 3) + 4];
            uint32_t a3 = sA[m0 + (lane >> 2) + 8][kk + (lane & 3) + 4];
#pragma unroll
            for (int nt = 0; nt < 4; nt++) {
                int n = n0 + nt * 8;
                uint32_t b0 = sB[n + (lane >> 2)][kk + (lane & 3)];
                uint32_t b1 = sB[n + (lane >> 2)][kk + (lane & 3) + 4];
                mma8(acc[nt], a0, a1, a2, a3, b0, b1);
            }
        }
    }
    __syncthreads();
#pragma unroll
    for (int nt = 0; nt < 4; nt++) {
        int col = n0 + nt * 8 + (lane & 3) * 2;
        int row = m0 + (lane >> 2);
        tile[row][col] = acc[nt][0];
        tile[row][col + 1] = acc[nt][1];
        tile[row + 8][col] = acc[nt][2];
        tile[row + 8][col + 1] = acc[nt][3];
    }
    __syncthreads();
#pragma unroll
    for (int rr = 0; rr < 8; rr++) {
        int row = w * 8 + rr;
        int grow = r0 + row;
#pragma unroll
        for (int i = 0; i < 2; i++) {
            int col = lane + i * 32;
            int gcol = n0g + col;
            if (gcol < C_) out[(size_t)grow * C_ + gcol] = tile[row][col] + bco[gcol];
        }
    }
}

// ---------------------------------------------------------------------------
extern "C" void kernel_launch(void* const* d_in, const int* in_sizes, int n_in,
                              void* d_out, int out_size) {
    (void)in_sizes; (void)n_in; (void)out_size;
    const float* x     = (const float*)d_in[0];
    const float* wfx_w = (const float*)d_in[1];
    const float* wfx_b = (const float*)d_in[2];
    const float* wix_w = (const float*)d_in[3];
    const float* wix_b = (const float*)d_in[4];
    const float* wox_w = (const float*)d_in[5];
    const float* wox_b = (const float*)d_in[6];
    const float* wcx_w = (const float*)d_in[7];
    const float* wcx_b = (const float*)d_in[8];
    const float* wfh_w = (const float*)d_in[9];
    const float* wih_w = (const float*)d_in[10];
    const float* woh_w = (const float*)d_in[11];
    const float* wch_w = (const float*)d_in[12];
    const float* fco_w = (const float*)d_in[13];
    const float* fco_b = (const float*)d_in[14];
    float* out = (float*)d_out;

    // Attribute set (idempotent, no allocation, capture-safe).
    cudaFuncSetAttribute(lstm_scan,
                         cudaFuncAttributeMaxDynamicSharedMemorySize,
                         SMEM_SCAN);

    prep_w<<<(4 * H_ * H_) / 256, 256>>>(wfh_w, wih_w, woh_w, wch_w);

    dim3 g1(16, T_ / TB);
    gates_gemm<<<g1, 256>>>(x, wfx_w, wix_w, wox_w, wcx_w,
                            wfx_b, wix_b, wox_b, wcx_b);

    lstm_scan<<<NBLK, 256, SMEM_SCAN>>>();

    dim3 g3(5, T_);
    out_gemm<<<g3, 256>>>(fco_w, fco_b, out);
}

// round 13
// speedup vs baseline: 1.1467x; 1.1467x over previous
#include <cuda_runtime.h>
#include <cstdint>
#include <cstddef>

#define T_ 512
#define B_ 64
#define F_ 256
#define H_ 1024
#define C_ 257
#define TB 4       // timesteps batched per gates_gemm block
#define NBLK 128   // scan blocks: quad (4i..4i+3) splits K for 32-wide h-tile i
#define NOWN 32    // owner blocks (blockIdx%4==0) -- the only barrier arrivers
#define NCH4 8     // K chunks of 32 per block (256 K per quarter)
#define WROWS 128  // gate-columns per block tile (4 gates x 32 h)
#define SCANT 512  // scan threads: 16 warps, 2 warp-groups K-splitting chunks
#define WSM_U32 (NCH4 * WROWS * 36)                   // 36864 u32 weight slab
#define ZSM_OFF (WSM_U32 + 4 * 64 * 36)               // after 4 A buffers
#define SMEM_SCAN ((ZSM_OFF + WROWS * 68) * 4)        // 219136 B dynamic smem

// Scratch (static __device__ arrays: allowed; no allocation APIs used).
__device__ float g_gates[(size_t)T_ * 4 * H_ * B_];  // [T][4][H][B]
__device__ float g_hs[(size_t)T_ * B_ * H_];         // [T][B][H], tf32-valued
__device__ float g_c[B_ * H_];                       // [B][H]
// Pre-converted tf32 recurrent weights, per (scan-block, K-chunk):
// g_wtf[((blk*NCH4 + kc)*WROWS + r)*32 + p]; blk = grp*4 + kq covers
// K quarter kq*256, h-tile grp (32 h); r = gate*32 + hh; p is the PERMUTED
// k position: within each 8-group, k sits at p = (k&3)*2 + (k>>2), so the
// mma B-fragment pair (k, k+4) is adjacent -> one lds.64.
__device__ uint32_t g_wtf[(size_t)4 * H_ * H_];
// Split-K partials: [grp][helper 0..2][tid 0..255 (wg0)][32 fragment regs].
__device__ float g_part[NBLK / 4][3][256][32];
// Group handoff flags (monotone across graph replays; compared relatively).
__device__ volatile unsigned int g_pflag[NBLK / 4];

// Grid-barrier state (replay-safe: arrive reset by last arriver; release is
// monotone, compared relatively). Only OWNER blocks arrive; all blocks wait.
__device__ unsigned int g_arrive;
__device__ volatile unsigned int g_release;

__device__ __forceinline__ uint32_t f2tf(float x) {
    uint32_t r;
    asm("cvt.rna.tf32.f32 %0, %1;" : "=r"(r) : "f"(x));
    return r;
}

// Fast tanh: clamped 2x-exp formula. |err| ~1e-6 (clamped tail < 1e-13).
__device__ __forceinline__ float tanh_fast(float x) {
    float xc = fminf(fmaxf(x, -15.0f), 15.0f);
    float e = __expf(2.0f * xc);
    return __fdividef(e - 1.0f, e + 1.0f);
}
__device__ __forceinline__ float sigmoid_fast(float x) {
    return __fdividef(1.0f, 1.0f + __expf(-x));
}

__device__ __forceinline__ void mma8(float* c, uint32_t a0, uint32_t a1, uint32_t a2,
                                     uint32_t a3, uint32_t b0, uint32_t b1) {
    asm volatile(
        "mma.sync.aligned.m16n8k8.row.col.f32.tf32.tf32.f32 "
        "{%0,%1,%2,%3},{%4,%5,%6,%7},{%8,%9},{%0,%1,%2,%3};"
        : "+f"(c[0]), "+f"(c[1]), "+f"(c[2]), "+f"(c[3])
        : "r"(a0), "r"(a1), "r"(a2), "r"(a3), "r"(b0), "r"(b1));
}

// Device-wide step barrier: owners arrive (32 atomics), EVERY block waits for
// the release bump. Safe because helpers produce nothing cross-block except
// g_part, which the group owner consumes BEFORE arriving here, and a helper's
// next overwrite sits behind this release.
__device__ __forceinline__ void step_barrier(int tid, bool arriver) {
    __syncthreads();
    __threadfence();
    if (tid == 0) {
        unsigned int cur = g_release;
        if (arriver) {
            unsigned int old = atomicAdd(&g_arrive, 1u);
            if (old == NOWN - 1) {
                g_arrive = 0;             // no new arrivals until release bumps
                __threadfence();
                atomicAdd((unsigned int*)&g_release, 1u);
            } else {
                while (g_release == cur) {}
            }
        } else {
            while (g_release == cur) {}
        }
    }
    __syncthreads();
    __threadfence();
}

// ---------------------------------------------------------------------------
// Kernel 0: one-time recurrent-weight repack into tf32 (4-way split-K layout
// with the in-group k permutation; destination-indexed: p -> source k).
// ---------------------------------------------------------------------------
__global__ __launch_bounds__(256) void prep_w(
    const float* __restrict__ whf, const float* __restrict__ whi,
    const float* __restrict__ who, const float* __restrict__ whc) {
    size_t idx = (size_t)blockIdx.x * 256 + threadIdx.x;  // < 4*H*H
    int blk = (int)(idx >> 15);         // 128 slabs of 32768
    int rem = (int)(idx & 32767);
    int kc = rem >> 12;                 // chunk 0..7 (4096 elems each)
    int r = (rem >> 5) & 127;           // gate-col within 128-wide tile
    int p = rem & 31;                   // PERMUTED k position within chunk
    int pp = p & 7;
    int k = (p >> 3) * 8 + (pp >> 1) + (pp & 1) * 4;  // inverse permutation
    int g = r >> 5, hh = r & 31;
    int grp = blk >> 2, kq = blk & 3;
    int kglob = kq * 256 + kc * 32 + k;
    int hrow = grp * 32 + hh;
    const float* wp = (g == 0) ? whf : (g == 1) ? whi : (g == 2) ? who : whc;
    g_wtf[idx] = f2tf(wp[(size_t)hrow * H_ + kglob]);
}

// ---------------------------------------------------------------------------
// Kernel 1: gates GEMM.  g_gates[t][g][h][b] = x[t][b][:] . Wg[h][:] + bg[h]
// Grid: (16 h-tiles of 64, 128 t-batches of TB=4); gate-outer, t-inner so each
// gate's weight tile is pulled from L2 once, re-staged from L1 for TB-1 steps.
// ---------------------------------------------------------------------------
__global__ __launch_bounds__(256) void gates_gemm(
    const float* __restrict__ x,
    const float* __restrict__ w0, const float* __restrict__ w1,
    const float* __restrict__ w2, const float* __restrict__ w3,
    const float* __restrict__ bb0, const float* __restrict__ bb1,
    const float* __restrict__ bb2, const float* __restrict__ bb3) {
    __shared__ __align__(16) uint32_t sA[64][36];
    __shared__ __align__(16) uint32_t sB[64][36];
    __shared__ float tile[64][65];

    const int t0 = blockIdx.y * TB, h0 = blockIdx.x * 64;
    const int tid = threadIdx.x, lane = tid & 31, w = tid >> 5;
    const int m0 = (w & 3) * 16, n0 = (w >> 2) * 32;

    for (int g = 0; g < 4; g++) {
        const float* wg = (g == 0) ? w0 : (g == 1) ? w1 : (g == 2) ? w2 : w3;
        const float* bg = (g == 0) ? bb0 : (g == 1) ? bb1 : (g == 2) ? bb2 : bb3;

        for (int tt = 0; tt < TB; tt++) {
            const int t = t0 + tt;
            float acc[4][4] = {};

            for (int kc = 0; kc < F_; kc += 32) {
                __syncthreads();
#pragma unroll
                for (int i = 0; i < 2; i++) {
                    int idx = tid + i * 256;
                    int r = idx >> 3, q = idx & 7;
                    float4 v = *(const float4*)
                        &x[((size_t)t * 64 + r) * F_ + kc + q * 4];
                    uint32_t* d = &sA[r][q * 4];
                    d[0] = f2tf(v.x); d[1] = f2tf(v.y);
                    d[2] = f2tf(v.z); d[3] = f2tf(v.w);
                    float4 u = *(const float4*)
                        &wg[(size_t)(h0 + r) * F_ + kc + q * 4];
                    uint32_t* e = &sB[r][q * 4];
                    e[0] = f2tf(u.x); e[1] = f2tf(u.y);
                    e[2] = f2tf(u.z); e[3] = f2tf(u.w);
                }
                __syncthreads();
#pragma unroll
                for (int ks = 0; ks < 4; ks++) {
                    int kk = ks * 8;
                    uint32_t a0 = sA[m0 + (lane >> 2)][kk + (lane & 3)];
                    uint32_t a1 = sA[m0 + (lane >> 2) + 8][kk + (lane & 3)];
                    uint32_t a2 = sA[m0 + (lane >> 2)][kk + (lane & 3) + 4];
                    uint32_t a3 = sA[m0 + (lane >> 2) + 8][kk + (lane & 3) + 4];
#pragma unroll
                    for (int nt = 0; nt < 4; nt++) {
                        int n = n0 + nt * 8;
                        uint32_t b0 = sB[n + (lane >> 2)][kk + (lane & 3)];
                        uint32_t b1 = sB[n + (lane >> 2)][kk + (lane & 3) + 4];
                        mma8(acc[nt], a0, a1, a2, a3, b0, b1);
                    }
                }
            }
            __syncthreads();
#pragma unroll
            for (int nt = 0; nt < 4; nt++) {
                int col = n0 + nt * 8 + (lane & 3) * 2;
                int row = m0 + (lane >> 2);
                tile[row][col] = acc[nt][0];
                tile[row][col + 1] = acc[nt][1];
                tile[row + 8][col] = acc[nt][2];
                tile[row + 8][col + 1] = acc[nt][3];
            }
            __syncthreads();
            // Transposed, coalesced store into [T][4][H][B] layout + bias.
#pragma unroll
            for (int hh = 0; hh < 8; hh++) {
                int h = w * 8 + hh;
                float bv = bg[h0 + h];
                float* dst = &g_gates[(((size_t)t * 4 + g) * H_ + h0 + h) * 64];
                dst[lane] = tile[lane][h] + bv;
                dst[lane + 32] = tile[lane + 32][h] + bv;
            }
        }
    }
}

// ---------------------------------------------------------------------------
// Kernel 2: persistent LSTM scan. 128 blocks (1/SM) x 512 threads (16 warps).
// Quad (4i..4i+3) owns 32-wide h-tile i with 4-way split-K (256 K each).
// Within a block, warp-group 0 (warps 0-7) processes even K-chunks and
// warp-group 1 odd chunks (warp-level K-split: doubles warps hiding HMMA/LDS
// latency -- the measured bottleneck -- without changing the m32n32 tiles).
// wg1's partial folds into wg0 through zsm. Weights resident in smem (144KB);
// per-wg A double-buffers (4 x 9KB); separate zsm. Helpers ship wg0-folded
// fragments via g_part + group flag; owner folds, runs elementwise, writes
// h & c. Owners-arrive step barrier between steps.
// ---------------------------------------------------------------------------
__global__ __launch_bounds__(SCANT) void lstm_scan() {
    extern __shared__ __align__(16) uint32_t dyn[];
    uint32_t* wsm = dyn;                                // [NCH4*128][36]
    uint32_t (*sAb)[64][36] = (uint32_t (*)[64][36])(dyn + WSM_U32);  // [4]
    float* zsm = (float*)(dyn + ZSM_OFF);               // [128][68]

    const int tid = threadIdx.x, lane = tid & 31, w = tid >> 5;
    const int wgp = w >> 3;             // warp-group: 0 = even chunks, 1 = odd
    const int wl = w & 7;
    const int m0 = (wl & 1) * 32;       // 2 m-positions (b)
    const int n0 = (wl >> 1) * 32;      // 4 n-positions (j)
    const int grp = blockIdx.x >> 2;
    const int sub = blockIdx.x & 3;
    const bool owner = (sub == 0);
    const int h0 = grp * 32;
    const int koff = sub * 256;

    // Staging: thread group sg (= wgp, since tid<256 <=> w<8) stages its own
    // warp-group's chunks; 256 threads cover 64 rows x 8 quads in two waves.
    const int sg = tid >> 8;
    const int g_tid = tid & 255;
    const int r_s = g_tid >> 3, q_s = g_tid & 7;
    const int r_s2 = r_s + 32;
    const uint32_t* wblk = g_wtf + (size_t)blockIdx.x * (NCH4 * WROWS * 32);

    // Per-thread fragment coordinates (mma C mapping), fragment fi = mt*4+nt.
    const int frow = lane >> 2;         // + m0 + mt*16 (+8)
    const int fcol = (lane & 3) * 2;    // + n0 + nt*8 (+1)

    // Replay-safe flag base (read before any helper increment can occur).
    const unsigned int flagbase = g_pflag[grp];

    // One-time weight preload: slab rows (32 u32) -> padded smem rows (36).
    for (int i = tid; i < NCH4 * WROWS * 8; i += SCANT) {
        int row = i >> 3, s8 = i & 7;
        *(uint4*)&wsm[row * 36 + s8 * 4] =
            *(const uint4*)&wblk[(size_t)row * 32 + s8 * 4];
    }

    // gx fragment for the CURRENT step (owner wg0 only -- holds final acc).
    float gxr[8][4];
    if (owner && wgp == 0) {
#pragma unroll
        for (int mt = 0; mt < 2; mt++)
#pragma unroll
            for (int nt = 0; nt < 4; nt++)
#pragma unroll
                for (int p = 0; p < 4; p++) {
                    int row = m0 + mt * 16 + frow + (p >> 1) * 8;
                    int col = n0 + nt * 8 + fcol + (p & 1);
                    int g = col >> 5, hh = col & 31;
                    gxr[mt * 4 + nt][p] =
                        g_gates[(((size_t)g) * H_ + h0 + hh) * 64 + row];
                }
    }
    __syncthreads();   // wsm visible to all warps before any mma

    for (int t = 0; t < T_; t++) {
        float acc[8][4] = {};

        if (t > 0) {
            const uint32_t* hp =
                (const uint32_t*)&g_hs[(size_t)(t - 1) * B_ * H_] + koff;

            // Prologue: stage chunk sg (round 0's chunk for wg sg) into
            // buffer [sg][0] (A is the only per-step dependency).
            *(uint4*)&sAb[sg * 2][r_s][q_s * 4] =
                *(const uint4*)&hp[(size_t)r_s * H_ + sg * 32 + q_s * 4];
            *(uint4*)&sAb[sg * 2][r_s2][q_s * 4] =
                *(const uint4*)&hp[(size_t)r_s2 * H_ + sg * 32 + q_s * 4];
            __syncthreads();

            for (int r = 0; r < 4; r++) {          // rounds: 2 chunks each
                const int cur = r & 1, nxt = cur ^ 1;
                uint4 va0, va1;
                if (r < 3) {
                    int k0 = (2 * (r + 1) + sg) * 32;
                    va0 = *(const uint4*)&hp[(size_t)r_s * H_ + k0 + q_s * 4];
                    va1 = *(const uint4*)&hp[(size_t)r_s2 * H_ + k0 + q_s * 4];
                }
                const int c = 2 * r + wgp;          // this wg's chunk
                const uint32_t* wrow = &wsm[c * WROWS * 36];
                const uint32_t (*Ab)[36] = sAb[wgp * 2 + cur];
#pragma unroll
                for (int ks = 0; ks < 4; ks++) {
                    int kk = ks * 8;
#pragma unroll
                    for (int mt = 0; mt < 2; mt++) {
                        int mr = m0 + mt * 16 + frow;
                        uint32_t a0 = Ab[mr][kk + (lane & 3)];
                        uint32_t a1 = Ab[mr + 8][kk + (lane & 3)];
                        uint32_t a2 = Ab[mr][kk + (lane & 3) + 4];
                        uint32_t a3 = Ab[mr + 8][kk + (lane & 3) + 4];
#pragma unroll
                        for (int nt = 0; nt < 4; nt++) {
                            int n = n0 + nt * 8;
                            // Permuted resident weights: (k,k+4) -> lds.64.
                            uint2 bb = *(const uint2*)
                                &wrow[(n + frow) * 36 + kk + (lane & 3) * 2];
                            mma8(acc[mt * 4 + nt], a0, a1, a2, a3, bb.x, bb.y);
                        }
                    }
                }
                if (r < 3) {
                    *(uint4*)&sAb[sg * 2 + nxt][r_s][q_s * 4] = va0;
                    *(uint4*)&sAb[sg * 2 + nxt][r_s2][q_s * 4] = va1;
                }
                __syncthreads();
            }
        } else {
            __syncthreads();
        }

        // Fold wg1's partial into wg0 through zsm (positions coincide: wg0
        // warp wl and wg1 warp wl share (m0, n0)).
        if (t > 0 && wgp == 1) {
#pragma unroll
            for (int mt = 0; mt < 2; mt++)
#pragma unroll
                for (int nt = 0; nt < 4; nt++) {
                    int fi = mt * 4 + nt;
                    int row = m0 + mt * 16 + frow;
                    int col = n0 + nt * 8 + fcol;
                    zsm[(size_t)col * 68 + row] = acc[fi][0];
                    zsm[(size_t)(col + 1) * 68 + row] = acc[fi][1];
                    zsm[(size_t)col * 68 + row + 8] = acc[fi][2];
                    zsm[(size_t)(col + 1) * 68 + row + 8] = acc[fi][3];
                }
        }
        __syncthreads();
        if (t > 0 && wgp == 0) {
#pragma unroll
            for (int mt = 0; mt < 2; mt++)
#pragma unroll
                for (int nt = 0; nt < 4; nt++) {
                    int fi = mt * 4 + nt;
                    int row = m0 + mt * 16 + frow;
                    int col = n0 + nt * 8 + fcol;
                    acc[fi][0] += zsm[(size_t)col * 68 + row];
                    acc[fi][1] += zsm[(size_t)(col + 1) * 68 + row];
                    acc[fi][2] += zsm[(size_t)col * 68 + row + 8];
                    acc[fi][3] += zsm[(size_t)(col + 1) * 68 + row + 8];
                }
        }

        if (!owner) {
            // Helper: wg0 ships the folded fragment, then flag, then barrier.
            if (t > 0 && wgp == 0) {
                float* dst = g_part[grp][sub - 1][tid];   // tid < 256 here
#pragma unroll
                for (int fi = 0; fi < 8; fi++)
                    *(float4*)&dst[fi * 4] = *(float4*)acc[fi];
            }
            __syncthreads();
            if (t > 0 && tid == 0) {
                __threadfence();
                atomicAdd((unsigned int*)&g_pflag[grp], 1u);
            }
        } else {
            // Owner: wait for 3 helpers, fold, then elementwise.
            if (t > 0 && tid == 0) {
                while ((unsigned int)(g_pflag[grp] - flagbase) <
                       3u * (unsigned int)t) {}
            }
            __syncthreads();
            __threadfence();
            if (t > 0 && wgp == 0) {
#pragma unroll
                for (int hlp = 0; hlp < 3; hlp++) {
                    const float* src = g_part[grp][hlp][tid];
#pragma unroll
                    for (int fi = 0; fi < 8; fi++) {
                        float4 pv = *(const float4*)&src[fi * 4];
                        acc[fi][0] += pv.x; acc[fi][1] += pv.y;
                        acc[fi][2] += pv.z; acc[fi][3] += pv.w;
                    }
                }
            }
            // z = gx + rec into zsm (wg0 holds the complete sum; at t==0
            // acc==0 so z = gx). Ordered after the fold-read by the barrier
            // above.
            if (wgp == 0) {
#pragma unroll
                for (int mt = 0; mt < 2; mt++)
#pragma unroll
                    for (int nt = 0; nt < 4; nt++) {
                        int fi = mt * 4 + nt;
                        int row = m0 + mt * 16 + frow;
                        int col = n0 + nt * 8 + fcol;
                        zsm[(size_t)col * 68 + row] = acc[fi][0] + gxr[fi][0];
                        zsm[(size_t)(col + 1) * 68 + row] =
                            acc[fi][1] + gxr[fi][1];
                        zsm[(size_t)col * 68 + row + 8] =
                            acc[fi][2] + gxr[fi][2];
                        zsm[(size_t)(col + 1) * 68 + row + 8] =
                            acc[fi][3] + gxr[fi][3];
                    }
            }
            __syncthreads();

            // Fused elementwise cell update over 32 h x 64 b by all 512
            // threads (4 elements each). j = g*32 + h; gate order f, i, o, a.
            const int b = tid >> 3, hsub = tid & 7;
#pragma unroll
            for (int ii = 0; ii < 4; ii++) {
                int h = hsub + ii * 8;  // 0..31
                float zf = zsm[(size_t)h * 68 + b];
                float zi = zsm[(size_t)(32 + h) * 68 + b];
                float zo = zsm[(size_t)(64 + h) * 68 + b];
                float za = zsm[(size_t)(96 + h) * 68 + b];
                float ft = sigmoid_fast(zf);
                float it = sigmoid_fast(zi);
                float ot = sigmoid_fast(zo);
                int hidx = h0 + h;
                float cold = (t == 0) ? 0.0f : g_c[b * H_ + hidx];
                float cn = it * tanh_fast(za) + ft * cold;
                float hn = ot * tanh_fast(cn);
                g_c[b * H_ + hidx] = cn;
                // tf32-rounded h: next step's A staging is a raw bit copy.
                g_hs[((size_t)t * B_ + b) * H_ + hidx] =
                    __uint_as_float(f2tf(hn));
            }
        }

        if (t < T_ - 1) {
            // Cross-barrier prefetch of next step's gx (static source).
            if (owner && wgp == 0) {
#pragma unroll
                for (int mt = 0; mt < 2; mt++)
#pragma unroll
                    for (int nt = 0; nt < 4; nt++)
#pragma unroll
                        for (int p = 0; p < 4; p++) {
                            int row = m0 + mt * 16 + frow + (p >> 1) * 8;
                            int col = n0 + nt * 8 + fcol + (p & 1);
                            int g = col >> 5, hh = col & 31;
                            gxr[mt * 4 + nt][p] = g_gates[
                                (((size_t)(t + 1) * 4 + g) * H_ + h0 + hh) * 64
                                + row];
                        }
            }
            step_barrier(tid, owner);
        }
    }
}

// ---------------------------------------------------------------------------
// Kernel 3: output GEMM.  out[row][c] = hs[row][:] . fco_w[c][:] + fco_b[c]
// Grid: (5 n-tiles of 64 covering C=257, 512 m-tiles of 64).
// ---------------------------------------------------------------------------
__global__ __launch_bounds__(256) void out_gemm(
    const float* __restrict__ wco, const float* __restrict__ bco,
    float* __restrict__ out) {
    __shared__ __align__(16) uint32_t sA[64][36];
    __shared__ __align__(16) uint32_t sB[64][36];
    __shared__ float tile[64][65];

    const int r0 = blockIdx.y * 64;
    const int n0g = blockIdx.x * 64;
    const int tid = threadIdx.x, lane = tid & 31, w = tid >> 5;
    const int m0 = (w & 3) * 16, n0 = (w >> 2) * 32;
    float acc[4][4] = {};

    for (int kc = 0; kc < H_; kc += 32) {
        __syncthreads();
#pragma unroll
        for (int i = 0; i < 2; i++) {
            int idx = tid + i * 256;
            int r = idx >> 3, q = idx & 7;
            *(uint4*)&sA[r][q * 4] = *(const uint4*)
                &g_hs[(size_t)(r0 + r) * H_ + kc + q * 4];
            int nr = n0g + r;
            float4 u = (nr < C_) ? *(const float4*)&wco[(size_t)nr * H_ + kc + q * 4]
                                 : make_float4(0.f, 0.f, 0.f, 0.f);
            uint32_t* e = &sB[r][q * 4];
            e[0] = f2tf(u.x); e[1] = f2tf(u.y); e[2] = f2tf(u.z); e[3] = f2tf(u.w);
        }
        __syncthreads();
#pragma unroll
        for (int ks = 0; ks < 4; ks++) {
            int kk = ks * 8;
            uint32_t a0 = sA[m0 + (lane >> 2)][kk + (lane & 3)];
            uint32_t a1 = sA[m0 + (lane >> 2) + 8][kk + (lane & 3)];
            uint32_t a2 = sA[m0 + (lane >> 2)][kk + (lane & 3) + 4];
            uint32_t a3 = sA[m0 + (lane >> 2) + 8][kk + (lane & 3) + 4];
#pragma unroll
            for (int nt = 0; nt < 4; nt++) {
                int n = n0 + nt * 8;
                uint32_t b0 = sB[n + (lane >> 2)][kk + (lane & 3)];
                uint32_t b1 = sB[n + (lane >> 2)][kk + (lane & 3) + 4];
                mma8(acc[nt], a0, a1, a2, a3, b0, b1);
            }
        }
    }
    __syncthreads();
#pragma unroll
    for (int nt = 0; nt < 4; nt++) {
        int col = n0 + nt * 8 + (lane & 3) * 2;
        int row = m0 + (lane >> 2);
        tile[row][col] = acc[nt][0];
        tile[row][col + 1] = acc[nt][1];
        tile[row + 8][col] = acc[nt][2];
        tile[row + 8][col + 1] = acc[nt][3];
    }
    __syncthreads();
#pragma unroll
    for (int rr = 0; rr < 8; rr++) {
        int row = w * 8 + rr;
        int grow = r0 + row;
#pragma unroll
        for (int i = 0; i < 2; i++) {
            int col = lane + i * 32;
            int gcol = n0g + col;
            if (gcol < C_) out[(size_t)grow * C_ + gcol] = tile[row][col] + bco[gcol];
        }
    }
}

// ---------------------------------------------------------------------------
extern "C" void kernel_launch(void* const* d_in, const int* in_sizes, int n_in,
                              void* d_out, int out_size) {
    (void)in_sizes; (void)n_in; (void)out_size;
    const float* x     = (const float*)d_in[0];
    const float* wfx_w = (const float*)d_in[1];
    const float* wfx_b = (const float*)d_in[2];
    const float* wix_w = (const float*)d_in[3];
    const float* wix_b = (const float*)d_in[4];
    const float* wox_w = (const float*)d_in[5];
    const float* wox_b = (const float*)d_in[6];
    const float* wcx_w = (const float*)d_in[7];
    const float* wcx_b = (const float*)d_in[8];
    const float* wfh_w = (const float*)d_in[9];
    const float* wih_w = (const float*)d_in[10];
    const float* woh_w = (const float*)d_in[11];
    const float* wch_w = (const float*)d_in[12];
    const float* fco_w = (const float*)d_in[13];
    const float* fco_b = (const float*)d_in[14];
    float* out = (float*)d_out;

    // Attribute set (idempotent, no allocation, capture-safe).
    cudaFuncSetAttribute(lstm_scan,
                         cudaFuncAttributeMaxDynamicSharedMemorySize,
                         SMEM_SCAN);

    prep_w<<<(4 * H_ * H_) / 256, 256>>>(wfh_w, wih_w, woh_w, wch_w);

    dim3 g1(16, T_ / TB);
    gates_gemm<<<g1, 256>>>(x, wfx_w, wix_w, wox_w, wcx_w,
                            wfx_b, wix_b, wox_b, wcx_b);

    lstm_scan<<<NBLK, SCANT, SMEM_SCAN>>>();

    dim3 g3(5, T_);
    out_gemm<<<g3, 256>>>(fco_w, fco_b, out);
}